// round 1
// baseline (speedup 1.0000x reference)
#include <cuda_runtime.h>
#include <math.h>

#define BB   4
#define TT   250
#define NS   100
#define DEP  64
#define SS   64000
#define NROW (BB*TT*NS)      // 100000 frame-rows
#define NSEQ (BB*NS)         // 400 scan sequences

// associative_scan levels (level "0" here = pairwise sums of the 64000 omegas)
#define NLVL 15
__constant__ int c_off[NLVL] = {0,32000,48000,56000,60000,62000,63000,63500,
                                63750,63875,63937,63968,63983,63990,63993};
__constant__ int c_sz[NLVL]  = {32000,16000,8000,4000,2000,1000,500,250,
                                125,62,31,15,7,3,1};
#define SCAN_STRIDE 63994

__device__ float g_freq[NROW];
__device__ float g_amp[NROW];
__device__ float g_scan[(size_t)NSEQ * SCAN_STRIDE];

// omega(s) for s = k*256 + r, mirroring jax fp32 ops exactly (no FMA contraction)
__device__ __forceinline__ float omega_val(float x0, float x1, int r) {
    float frac = __fmul_rn((float)r, 0.00390625f);                 // r/256, exact
    float fe   = __fadd_rn(__fmul_rn(x0, __fsub_rn(1.0f, frac)),
                           __fmul_rn(x1, frac));
    return __fmul_rn(fe, (float)(6.283185307179586 / 16000.0));   // * 2pi/sr (f32 const)
}

// ---------------------------------------------------------------------------
// frequencies_softmax + unit_to_hz : one warp per (b,t,n) row of 64 logits
// ---------------------------------------------------------------------------
__global__ void freq_kernel(const float* __restrict__ logits) {
    int row  = blockIdx.x * (blockDim.x >> 5) + (threadIdx.x >> 5);
    int lane = threadIdx.x & 31;
    if (row >= NROW) return;
    const float* x = logits + (size_t)row * DEP;

    float x0 = x[lane], x1 = x[lane + 32];
    float m = fmaxf(x0, x1);
    #pragma unroll
    for (int o = 16; o; o >>= 1) m = fmaxf(m, __shfl_xor_sync(0xffffffffu, m, o));

    // fp32 exp (matches XLA-GPU __nv_expf), double accumulation (near-correctly-rounded)
    float e0 = expf(__fsub_rn(x0, m));
    float e1 = expf(__fsub_rn(x1, m));
    double se  = (double)e0 + (double)e1;
    double seb = (double)e0 * ((double)lane / 63.0)
               + (double)e1 * ((double)(lane + 32) / 63.0);
    #pragma unroll
    for (int o = 16; o; o >>= 1) {
        se  += __shfl_xor_sync(0xffffffffu, se,  o);
        seb += __shfl_xor_sync(0xffffffffu, seb, o);
    }
    if (lane == 0) {
        float fu = (float)(seb / se);
        double mmin_d = 69.0 + 12.0 * log2(20.0   / 440.0);
        double mmax_d = 69.0 + 12.0 * log2(8000.0 / 440.0);
        float mminf = (float)mmin_d;
        float mdelf = (float)(mmax_d - mmin_d);
        float midi  = __fadd_rn(mminf, __fmul_rn(fu, mdelf));
        float ex    = __fdiv_rn(__fsub_rn(midi, 69.0f), 12.0f);
        float hz    = __fmul_rn(440.0f, powf(2.0f, ex));
        g_freq[row] = hz;
    }
}

// ---------------------------------------------------------------------------
// exp_sigmoid(amplitudes) * (freq < nyquist)
// ---------------------------------------------------------------------------
__global__ void amp_kernel(const float* __restrict__ amp_in) {
    int i = blockIdx.x * blockDim.x + threadIdx.x;
    if (i >= NROW) return;
    float xv = amp_in[i];
    float sg = __fdiv_rn(1.0f, __fadd_rn(1.0f, expf(-xv)));
    float p  = powf(sg, (float)2.302585092994046);     // log(10) in f32
    float a  = __fadd_rn(__fmul_rn(2.0f, p), 1e-7f);
    if (!(g_freq[i] < 8000.0f)) a = 0.0f;
    g_amp[i] = a;
}

// ---------------------------------------------------------------------------
// Exact replication of jax.lax.associative_scan(add) over 64000 omegas,
// one block per (b,n) sequence. Level 0 (omegas) is recomputed analytically;
// levels 1.. live in global scratch; downsweep is in-place.
// ---------------------------------------------------------------------------
__global__ void __launch_bounds__(1024, 1) scan_kernel() {
    int seq = blockIdx.x;
    int b = seq / NS, n = seq % NS;

    __shared__ float fr[TT + 1];
    for (int t = threadIdx.x; t < TT; t += blockDim.x)
        fr[t] = g_freq[(b * TT + t) * NS + n];
    __syncthreads();
    if (threadIdx.x == 0) fr[TT] = fr[TT - 1];   // endpoint clip (i1 = min(i0+1, T-1))
    __syncthreads();

    float* buf = g_scan + (size_t)seq * SCAN_STRIDE;

    // build level 1: a1[i] = omega(2i) + omega(2i+1); both samples share frame k
    for (int i = threadIdx.x; i < 32000; i += blockDim.x) {
        int s = 2 * i;
        int k = s >> 8, r = s & 255;
        float x0 = fr[k], x1 = fr[k + 1];
        buf[i] = __fadd_rn(omega_val(x0, x1, r), omega_val(x0, x1, r + 1));
    }
    __syncthreads();

    // upsweep
    for (int lvl = 0; lvl + 1 < NLVL; ++lvl) {
        const float* src = buf + c_off[lvl];
        float*       dst = buf + c_off[lvl + 1];
        int m = c_sz[lvl + 1];
        for (int i = threadIdx.x; i < m; i += blockDim.x)
            dst[i] = __fadd_rn(src[2 * i], src[2 * i + 1]);
        __syncthreads();
    }

    // downsweep (in-place: each thread reads only its own a[j])
    for (int lvl = NLVL - 2; lvl >= 0; --lvl) {
        float*       a  = buf + c_off[lvl];
        const float* sc = buf + c_off[lvl + 1];
        int nl = c_sz[lvl];
        for (int j = threadIdx.x; j < nl; j += blockDim.x) {
            float v;
            if (j & 1)        v = sc[j >> 1];
            else if (j == 0)  v = a[0];
            else              v = __fadd_rn(sc[(j >> 1) - 1], a[j]);
            a[j] = v;
        }
        __syncthreads();
    }
    // buf[c_off[0] + i] now holds S_{2i+1} (prefix sums at odd sample positions)
}

// ---------------------------------------------------------------------------
// Output: one block = one (b, frame k) -> 256 samples; loop over 100 sinusoids
// phase: s odd  -> scan1[s>>1]
//        s even -> scan1[(s>>1)-1] + omega(s)   (s==0 -> omega(0))
// ---------------------------------------------------------------------------
__global__ void out_kernel(float* __restrict__ out) {
    int blk = blockIdx.x;            // 0 .. B*TT-1
    int b = blk / TT, k = blk % TT;
    int r = threadIdx.x;             // 0..255

    __shared__ float f0s[NS], f1s[NS], a0s[NS], a1s[NS];
    int k1 = (k + 1 < TT) ? (k + 1) : (TT - 1);
    for (int n = threadIdx.x; n < NS; n += blockDim.x) {
        f0s[n] = g_freq[(b * TT + k ) * NS + n];
        f1s[n] = g_freq[(b * TT + k1) * NS + n];
        a0s[n] = g_amp [(b * TT + k ) * NS + n];
        a1s[n] = g_amp [(b * TT + k1) * NS + n];
    }
    __syncthreads();

    int s = k * 256 + r;
    float rf   = (float)r;
    float warg = __fdiv_rn(__fmul_rn((float)3.141592653589793, rf), 256.0f);
    float w    = __fsub_rn(0.5f, __fmul_rn(0.5f, cosf(warg)));
    float omw  = __fsub_rn(1.0f, w);
    bool  odd  = (s & 1);
    int   idx  = odd ? (s >> 1) : ((s >> 1) - 1);

    float acc = 0.0f;
    const float* base = g_scan + (size_t)(b * NS) * SCAN_STRIDE;
    #pragma unroll 4
    for (int n = 0; n < NS; ++n) {
        const float* buf = base + (size_t)n * SCAN_STRIDE;
        float ph;
        if (odd) {
            ph = buf[idx];
        } else {
            float om = omega_val(f0s[n], f1s[n], r);
            ph = (s == 0) ? om : __fadd_rn(buf[idx], om);
        }
        float ae = __fadd_rn(__fmul_rn(a0s[n], omw), __fmul_rn(a1s[n], w));
        acc = __fadd_rn(acc, __fmul_rn(ae, sinf(ph)));
    }
    out[b * SS + s] = acc;
}

// ---------------------------------------------------------------------------
extern "C" void kernel_launch(void* const* d_in, const int* in_sizes, int n_in,
                              void* d_out, int out_size) {
    const float* amps  = (const float*)d_in[0];   // [4,250,100]   = 100000
    const float* freqs = (const float*)d_in[1];   // [4,250,6400]  = 6400000
    if (n_in >= 2 && in_sizes[0] > in_sizes[1]) { // safety: identify by size
        const float* t = amps; amps = freqs; freqs = t;
    }
    freq_kernel<<<(NROW + 7) / 8, 256>>>(freqs);  // 8 warps/block, 1 row/warp
    amp_kernel<<<(NROW + 255) / 256, 256>>>(amps);
    scan_kernel<<<NSEQ, 1024>>>();
    out_kernel<<<BB * TT, 256>>>((float*)d_out);
}

// round 2
// speedup vs baseline: 1.1053x; 1.1053x over previous
#include <cuda_runtime.h>
#include <math.h>

#define BB   4
#define TT   250
#define NS   100
#define DEP  64
#define SS   64000
#define NROW (BB*TT*NS)      // 100000 frame-rows
#define NSEQ (BB*NS)         // 400 scan sequences
#define L2N  16000           // level-2 scan length per sequence
#define NSPLIT 4
#define NPER (NS/NSPLIT)     // 25 sinusoids per partial

__device__ float g_freq[NROW];
__device__ float g_amp[NROW];
__device__ float g_scan2[(size_t)NSEQ * L2N];            // 25.6 MB
__device__ float g_part[(size_t)NSPLIT * BB * SS];       // 4 MB partial sums

// omega(s) for s = k*256 + r, mirroring jax fp32 ops exactly (no FMA contraction)
__device__ __forceinline__ float omega_val(float x0, float x1, int r) {
    float frac = __fmul_rn((float)r, 0.00390625f);                 // r/256, exact
    float fe   = __fadd_rn(__fmul_rn(x0, __fsub_rn(1.0f, frac)),
                           __fmul_rn(x1, frac));
    return __fmul_rn(fe, (float)(6.283185307179586 / 16000.0));   // * 2pi/sr (f32)
}

// ---------------------------------------------------------------------------
// controls: frequencies_softmax + unit_to_hz + exp_sigmoid + nyquist mask.
// One warp per (b,t,n) row of 64 logits; lane 0 also does the amp math.
// ---------------------------------------------------------------------------
__global__ void ctrl_kernel(const float* __restrict__ logits,
                            const float* __restrict__ amp_in) {
    int row  = blockIdx.x * (blockDim.x >> 5) + (threadIdx.x >> 5);
    int lane = threadIdx.x & 31;
    if (row >= NROW) return;
    const float* x = logits + (size_t)row * DEP;

    float x0 = x[lane], x1 = x[lane + 32];
    float m = fmaxf(x0, x1);
    #pragma unroll
    for (int o = 16; o; o >>= 1) m = fmaxf(m, __shfl_xor_sync(0xffffffffu, m, o));

    float e0 = expf(__fsub_rn(x0, m));
    float e1 = expf(__fsub_rn(x1, m));
    double se  = (double)e0 + (double)e1;
    double seb = (double)e0 * ((double)lane / 63.0)
               + (double)e1 * ((double)(lane + 32) / 63.0);
    #pragma unroll
    for (int o = 16; o; o >>= 1) {
        se  += __shfl_xor_sync(0xffffffffu, se,  o);
        seb += __shfl_xor_sync(0xffffffffu, seb, o);
    }
    if (lane == 0) {
        float fu = (float)(seb / se);
        double mmin_d = 69.0 + 12.0 * log2(20.0   / 440.0);
        double mmax_d = 69.0 + 12.0 * log2(8000.0 / 440.0);
        float mminf = (float)mmin_d;
        float mdelf = (float)(mmax_d - mmin_d);
        float midi  = __fadd_rn(mminf, __fmul_rn(fu, mdelf));
        float ex    = __fdiv_rn(__fsub_rn(midi, 69.0f), 12.0f);
        float hz    = __fmul_rn(440.0f, powf(2.0f, ex));
        g_freq[row] = hz;

        // exp_sigmoid(amplitudes) * (hz < nyquist)
        float xv = amp_in[row];
        float sg = __fdiv_rn(1.0f, __fadd_rn(1.0f, expf(-xv)));
        float p  = powf(sg, (float)2.302585092994046);     // log(10) in f32
        float a  = __fadd_rn(__fmul_rn(2.0f, p), 1e-7f);
        if (!(hz < 8000.0f)) a = 0.0f;
        g_amp[row] = a;
    }
}

// ---------------------------------------------------------------------------
// associative_scan replica, but only producing the level-2 inclusive scan
// (scan2[i] = S(4i+3)). All levels live in shared memory; the single global
// write is the final 16000-float scan2 per sequence.
// ---------------------------------------------------------------------------
__global__ void __launch_bounds__(1024, 1) scan_kernel() {
    extern __shared__ float sm[];            // 31994 level floats + fr[251]
    float* fr = sm + 31994;

    int seq = blockIdx.x;
    int b = seq / NS, n = seq % NS;
    int tid = threadIdx.x;

    for (int t = tid; t < TT; t += 1024)
        fr[t] = g_freq[(b * TT + t) * NS + n];
    __syncthreads();
    if (tid == 0) fr[TT] = fr[TT - 1];       // endpoint clip
    __syncthreads();

    // build level 2 directly: a2[i] = (o(4i)+o(4i+1)) + (o(4i+2)+o(4i+3));
    // all 4 samples share frame k (r <= 255).
    for (int i = tid; i < L2N; i += 1024) {
        int s = 4 * i;
        int k = s >> 8, r = s & 255;
        float x0 = fr[k], x1 = fr[k + 1];
        float o0 = omega_val(x0, x1, r);
        float o1 = omega_val(x0, x1, r + 1);
        float o2 = omega_val(x0, x1, r + 2);
        float o3 = omega_val(x0, x1, r + 3);
        sm[i] = __fadd_rn(__fadd_rn(o0, o1), __fadd_rn(o2, o3));
    }
    __syncthreads();

    // level geometry (runtime-computed; sizes halve with floor)
    int offs[14], szs[14];
    {
        int o = 0, s = L2N;
        #pragma unroll
        for (int l = 0; l < 14; ++l) { offs[l] = o; szs[l] = s; o += s; s >>= 1; }
    }

    // upsweep (levels 2..15, all smem)
    for (int l = 0; l < 13; ++l) {
        const float* src = sm + offs[l];
        float*       dst = sm + offs[l + 1];
        int m = szs[l + 1];
        for (int i = tid; i < m; i += 1024)
            dst[i] = __fadd_rn(src[2 * i], src[2 * i + 1]);
        __syncthreads();
    }

    // downsweep (in-place)
    for (int l = 12; l >= 0; --l) {
        float*       a  = sm + offs[l];
        const float* sc = sm + offs[l + 1];
        int nl = szs[l];
        for (int j = tid; j < nl; j += 1024) {
            float v;
            if (j & 1)        v = sc[j >> 1];
            else if (j == 0)  v = a[0];
            else              v = __fadd_rn(sc[(j >> 1) - 1], a[j]);
            a[j] = v;
        }
        __syncthreads();
    }

    // write scan2
    float* g = g_scan2 + (size_t)seq * L2N;
    for (int i = tid; i < L2N; i += 1024) g[i] = sm[i];
}

// ---------------------------------------------------------------------------
// output: thread = one scan2 cell (4 consecutive samples), block = 4 frames,
// blockIdx.z = n-split. Phase reconstruction is bit-identical to the full
// scan1 expansion:
//   P0 = bm1 + o0          (s=4q,   s>0; s==0 -> o0)
//   P1 = bm1 + (o0+o1)     (s=4q+1; q==0 -> o0+o1)
//   P2 = P1 + o2           (s=4q+2, incl. s==2)
//   P3 = scan2[q]          (s=4q+3)
// ---------------------------------------------------------------------------
__global__ void __launch_bounds__(256) out_kernel() {
    int fg = blockIdx.x;              // frame group: frames 4fg .. 4fg+3
    int b  = blockIdx.y;
    int sp = blockIdx.z;              // n-split
    int t  = threadIdx.x;

    __shared__ float fs[5 * NS], as[5 * NS];   // frames 4fg .. 4fg+4 (clamped)
    for (int i = t; i < 5 * NS; i += 256) {
        int fl = i / NS, nn = i % NS;
        int frame = 4 * fg + fl;
        if (frame > TT - 1) frame = TT - 1;
        fs[i] = g_freq[(b * TT + frame) * NS + nn];
        as[i] = g_amp [(b * TT + frame) * NS + nn];
    }
    __syncthreads();

    int kk = t >> 6, j = t & 63;
    int k  = 4 * fg + kk;
    if (k >= TT) return;              // tail block (fg==62): frames 250,251 idle

    int r0 = 4 * j;
    int q  = k * 64 + j;              // scan2 index of sample 4q..4q+3
    int s0 = k * 256 + r0;

    // hann crossfade weights for the 4 samples (matches pi*r/hop fp32 ops)
    float w[4], ow[4];
    #pragma unroll
    for (int i = 0; i < 4; ++i) {
        float rf = (float)(r0 + i);
        float warg = __fdiv_rn(__fmul_rn((float)3.141592653589793, rf), 256.0f);
        w[i]  = __fsub_rn(0.5f, __fmul_rn(0.5f, cosf(warg)));
        ow[i] = __fsub_rn(1.0f, w[i]);
    }

    const float* fp0 = fs + kk * NS;
    const float* fp1 = fs + (kk + 1) * NS;
    const float* ap0 = as + kk * NS;
    const float* ap1 = as + (kk + 1) * NS;

    int nb = sp * NPER;
    const float* buf = g_scan2 + ((size_t)(b * NS + nb)) * L2N + q;

    float acc0 = 0.f, acc1 = 0.f, acc2 = 0.f, acc3 = 0.f;
    #pragma unroll 2
    for (int m = 0; m < NPER; ++m) {
        int n = nb + m;
        float f0 = fp0[n], f1 = fp1[n];
        float bq  = buf[(size_t)m * L2N];
        float bm1 = (q > 0) ? buf[(size_t)m * L2N - 1] : 0.0f;

        float o0 = omega_val(f0, f1, r0);
        float o1 = omega_val(f0, f1, r0 + 1);
        float o2 = omega_val(f0, f1, r0 + 2);
        float t01 = __fadd_rn(o0, o1);

        float P0 = q ? __fadd_rn(bm1, o0)  : o0;
        float P1 = q ? __fadd_rn(bm1, t01) : t01;
        float P2 = __fadd_rn(P1, o2);
        float P3 = bq;

        float a0 = ap0[n], a1 = ap1[n];
        float ae0 = __fadd_rn(__fmul_rn(a0, ow[0]), __fmul_rn(a1, w[0]));
        float ae1 = __fadd_rn(__fmul_rn(a0, ow[1]), __fmul_rn(a1, w[1]));
        float ae2 = __fadd_rn(__fmul_rn(a0, ow[2]), __fmul_rn(a1, w[2]));
        float ae3 = __fadd_rn(__fmul_rn(a0, ow[3]), __fmul_rn(a1, w[3]));

        acc0 = __fadd_rn(acc0, __fmul_rn(ae0, sinf(P0)));
        acc1 = __fadd_rn(acc1, __fmul_rn(ae1, sinf(P1)));
        acc2 = __fadd_rn(acc2, __fmul_rn(ae2, sinf(P2)));
        acc3 = __fadd_rn(acc3, __fmul_rn(ae3, sinf(P3)));
    }

    float4 v; v.x = acc0; v.y = acc1; v.z = acc2; v.w = acc3;
    *(float4*)(g_part + ((size_t)(sp * BB + b)) * SS + s0) = v;
}

// ---------------------------------------------------------------------------
__global__ void comb_kernel(float* __restrict__ out) {
    int i = blockIdx.x * blockDim.x + threadIdx.x;
    if (i < BB * SS) {
        float v = __fadd_rn(__fadd_rn(__fadd_rn(
                      g_part[i],
                      g_part[(size_t)BB * SS + i]),
                      g_part[(size_t)2 * BB * SS + i]),
                      g_part[(size_t)3 * BB * SS + i]);
        out[i] = v;
    }
}

// ---------------------------------------------------------------------------
extern "C" void kernel_launch(void* const* d_in, const int* in_sizes, int n_in,
                              void* d_out, int out_size) {
    const float* amps  = (const float*)d_in[0];   // [4,250,100]
    const float* freqs = (const float*)d_in[1];   // [4,250,6400]
    if (n_in >= 2 && in_sizes[0] > in_sizes[1]) {
        const float* t = amps; amps = freqs; freqs = t;
    }

    static const size_t scan_smem = (31994 + 256) * sizeof(float);  // ~129 KB
    cudaFuncSetAttribute(scan_kernel,
                         cudaFuncAttributeMaxDynamicSharedMemorySize,
                         (int)scan_smem);

    ctrl_kernel<<<(NROW + 7) / 8, 256>>>(freqs, amps);
    scan_kernel<<<NSEQ, 1024, scan_smem>>>();
    out_kernel<<<dim3((TT + 3) / 4, BB, NSPLIT), 256>>>();
    comb_kernel<<<(BB * SS + 255) / 256, 256>>>((float*)d_out);
}

// round 3
// speedup vs baseline: 6.8368x; 6.1856x over previous
#include <cuda_runtime.h>
#include <math.h>

#define BB   4
#define TT   250
#define NS   100
#define DEP  64
#define SS   64000
#define NROW (BB*TT*NS)      // 100000 frame-rows
#define NSEQ (BB*NS)         // 400 scan sequences
#define L2N  16000           // level-2 scan length per sequence
#define NSPLIT 4
#define NPER (NS/NSPLIT)     // 25 sinusoids per partial
#define CTRL_ROWS 128        // rows per ctrl block

__device__ float g_freq[NROW];
__device__ float g_amp[NROW];
__device__ float g_scan2[(size_t)NSEQ * L2N];            // 25.6 MB
__device__ float g_part[(size_t)NSPLIT * BB * SS];       // 4 MB partial sums

// omega(s) for s = k*256 + r, mirroring jax fp32 ops exactly (no FMA contraction)
__device__ __forceinline__ float omega_val(float x0, float x1, int r) {
    float frac = __fmul_rn((float)r, 0.00390625f);                 // r/256, exact
    float fe   = __fadd_rn(__fmul_rn(x0, __fsub_rn(1.0f, frac)),
                           __fmul_rn(x1, frac));
    return __fmul_rn(fe, (float)(6.283185307179586 / 16000.0));   // * 2pi/sr (f32)
}

// ---------------------------------------------------------------------------
// controls: one THREAD per (b,t,n) row. Logit tile staged through padded smem.
// FP64 limited to: 64 dbins (once/block), 2 FP64 ops/elem accumulation, 1 DDIV.
// Compile-time midi constants (previously runtime double log2 -> ~600us!).
// ---------------------------------------------------------------------------
__global__ void __launch_bounds__(CTRL_ROWS) ctrl_kernel(
        const float* __restrict__ logits,
        const float* __restrict__ amp_in) {
    __shared__ float  sx[CTRL_ROWS * 65];        // stride 65: conflict-free
    __shared__ double dbins[DEP];

    int tid  = threadIdx.x;
    int base = blockIdx.x * CTRL_ROWS;
    int row  = base + tid;

    if (tid < DEP) dbins[tid] = (double)tid / 63.0;   // exact i/63 (validated)

    int nrows = NROW - base; if (nrows > CTRL_ROWS) nrows = CTRL_ROWS;
    int nelem = nrows * DEP;
    const float* src = logits + (size_t)base * DEP;
    for (int i = tid; i < nelem; i += CTRL_ROWS)
        sx[(i >> 6) * 65 + (i & 63)] = src[i];
    __syncthreads();

    if (row >= NROW) return;
    const float* x = sx + tid * 65;

    float m = x[0];
    #pragma unroll
    for (int j = 1; j < DEP; ++j) m = fmaxf(m, x[j]);

    double se = 0.0, seb = 0.0;
    #pragma unroll 8
    for (int j = 0; j < DEP; ++j) {
        float e = expf(__fsub_rn(x[j], m));
        double ed = (double)e;
        se  += ed;
        seb  = fma(ed, dbins[j], seb);
    }
    float fu = (float)(seb / se);

    // compile-time midi constants: 69 + 12*log2(20/440), delta to 8000Hz case
    const float mminf = (float)15.48682057635244;
    const float mdelf = (float)103.72627427729668;
    float midi = __fadd_rn(mminf, __fmul_rn(fu, mdelf));
    float ex   = __fdiv_rn(__fsub_rn(midi, 69.0f), 12.0f);
    float hz   = __fmul_rn(440.0f, powf(2.0f, ex));
    g_freq[row] = hz;

    // exp_sigmoid(amplitudes) * (hz < nyquist)
    float xv = amp_in[row];
    float sg = __fdiv_rn(1.0f, __fadd_rn(1.0f, expf(-xv)));
    float p  = powf(sg, (float)2.302585092994046);
    float a  = __fadd_rn(__fmul_rn(2.0f, p), 1e-7f);
    if (!(hz < 8000.0f)) a = 0.0f;
    g_amp[row] = a;
}

// ---------------------------------------------------------------------------
// associative_scan replica producing the level-2 inclusive scan in smem.
// ---------------------------------------------------------------------------
__global__ void __launch_bounds__(1024, 1) scan_kernel() {
    extern __shared__ float sm[];            // 31994 level floats + fr[251]
    float* fr = sm + 31994;

    int seq = blockIdx.x;
    int b = seq / NS, n = seq % NS;
    int tid = threadIdx.x;

    for (int t = tid; t < TT; t += 1024)
        fr[t] = g_freq[(b * TT + t) * NS + n];
    __syncthreads();
    if (tid == 0) fr[TT] = fr[TT - 1];       // endpoint clip
    __syncthreads();

    // build level 2 directly: a2[i] = (o0+o1)+(o2+o3); all 4 share frame k
    for (int i = tid; i < L2N; i += 1024) {
        int s = 4 * i;
        int k = s >> 8, r = s & 255;
        float x0 = fr[k], x1 = fr[k + 1];
        float o0 = omega_val(x0, x1, r);
        float o1 = omega_val(x0, x1, r + 1);
        float o2 = omega_val(x0, x1, r + 2);
        float o3 = omega_val(x0, x1, r + 3);
        sm[i] = __fadd_rn(__fadd_rn(o0, o1), __fadd_rn(o2, o3));
    }
    __syncthreads();

    int offs[14], szs[14];
    {
        int o = 0, s = L2N;
        #pragma unroll
        for (int l = 0; l < 14; ++l) { offs[l] = o; szs[l] = s; o += s; s >>= 1; }
    }

    for (int l = 0; l < 13; ++l) {                       // upsweep
        const float* srcp = sm + offs[l];
        float*       dst  = sm + offs[l + 1];
        int m = szs[l + 1];
        for (int i = tid; i < m; i += 1024)
            dst[i] = __fadd_rn(srcp[2 * i], srcp[2 * i + 1]);
        __syncthreads();
    }

    for (int l = 12; l >= 0; --l) {                      // downsweep, in-place
        float*       a  = sm + offs[l];
        const float* sc = sm + offs[l + 1];
        int nl = szs[l];
        for (int j = tid; j < nl; j += 1024) {
            float v;
            if (j & 1)        v = sc[j >> 1];
            else if (j == 0)  v = a[0];
            else              v = __fadd_rn(sc[(j >> 1) - 1], a[j]);
            a[j] = v;
        }
        __syncthreads();
    }

    float* g = g_scan2 + (size_t)seq * L2N;
    for (int i = tid; i < L2N; i += 1024) g[i] = sm[i];
}

// ---------------------------------------------------------------------------
// output: thread = one scan2 cell (4 samples); blockIdx.z = n-split.
// Phase reconstruction bit-identical to the full scan1 expansion.
// ---------------------------------------------------------------------------
__global__ void __launch_bounds__(256) out_kernel() {
    int fg = blockIdx.x;              // frames 4fg .. 4fg+3
    int b  = blockIdx.y;
    int sp = blockIdx.z;
    int t  = threadIdx.x;

    __shared__ float fs[5 * NS], as[5 * NS];
    for (int i = t; i < 5 * NS; i += 256) {
        int fl = i / NS, nn = i % NS;
        int frame = 4 * fg + fl;
        if (frame > TT - 1) frame = TT - 1;
        fs[i] = g_freq[(b * TT + frame) * NS + nn];
        as[i] = g_amp [(b * TT + frame) * NS + nn];
    }
    __syncthreads();

    int kk = t >> 6, j = t & 63;
    int k  = 4 * fg + kk;
    if (k >= TT) return;

    int r0 = 4 * j;
    int q  = k * 64 + j;
    int s0 = k * 256 + r0;

    float w[4], ow[4];
    #pragma unroll
    for (int i = 0; i < 4; ++i) {
        float rf = (float)(r0 + i);
        float warg = __fdiv_rn(__fmul_rn((float)3.141592653589793, rf), 256.0f);
        w[i]  = __fsub_rn(0.5f, __fmul_rn(0.5f, cosf(warg)));
        ow[i] = __fsub_rn(1.0f, w[i]);
    }

    const float* fp0 = fs + kk * NS;
    const float* fp1 = fs + (kk + 1) * NS;
    const float* ap0 = as + kk * NS;
    const float* ap1 = as + (kk + 1) * NS;

    int nb = sp * NPER;
    const float* buf = g_scan2 + ((size_t)(b * NS + nb)) * L2N + q;

    float acc0 = 0.f, acc1 = 0.f, acc2 = 0.f, acc3 = 0.f;
    #pragma unroll 2
    for (int m = 0; m < NPER; ++m) {
        int n = nb + m;
        float f0 = fp0[n], f1 = fp1[n];
        float bq  = buf[(size_t)m * L2N];
        float bm1 = (q > 0) ? buf[(size_t)m * L2N - 1] : 0.0f;

        float o0 = omega_val(f0, f1, r0);
        float o1 = omega_val(f0, f1, r0 + 1);
        float o2 = omega_val(f0, f1, r0 + 2);
        float t01 = __fadd_rn(o0, o1);

        float P0 = q ? __fadd_rn(bm1, o0)  : o0;
        float P1 = q ? __fadd_rn(bm1, t01) : t01;
        float P2 = __fadd_rn(P1, o2);
        float P3 = bq;

        float a0 = ap0[n], a1 = ap1[n];
        float ae0 = __fadd_rn(__fmul_rn(a0, ow[0]), __fmul_rn(a1, w[0]));
        float ae1 = __fadd_rn(__fmul_rn(a0, ow[1]), __fmul_rn(a1, w[1]));
        float ae2 = __fadd_rn(__fmul_rn(a0, ow[2]), __fmul_rn(a1, w[2]));
        float ae3 = __fadd_rn(__fmul_rn(a0, ow[3]), __fmul_rn(a1, w[3]));

        acc0 = __fadd_rn(acc0, __fmul_rn(ae0, sinf(P0)));
        acc1 = __fadd_rn(acc1, __fmul_rn(ae1, sinf(P1)));
        acc2 = __fadd_rn(acc2, __fmul_rn(ae2, sinf(P2)));
        acc3 = __fadd_rn(acc3, __fmul_rn(ae3, sinf(P3)));
    }

    float4 v; v.x = acc0; v.y = acc1; v.z = acc2; v.w = acc3;
    *(float4*)(g_part + ((size_t)(sp * BB + b)) * SS + s0) = v;
}

// ---------------------------------------------------------------------------
__global__ void comb_kernel(float* __restrict__ out) {
    int i = blockIdx.x * blockDim.x + threadIdx.x;
    if (i < BB * SS) {
        float v = __fadd_rn(__fadd_rn(__fadd_rn(
                      g_part[i],
                      g_part[(size_t)BB * SS + i]),
                      g_part[(size_t)2 * BB * SS + i]),
                      g_part[(size_t)3 * BB * SS + i]);
        out[i] = v;
    }
}

// ---------------------------------------------------------------------------
extern "C" void kernel_launch(void* const* d_in, const int* in_sizes, int n_in,
                              void* d_out, int out_size) {
    const float* amps  = (const float*)d_in[0];   // [4,250,100]
    const float* freqs = (const float*)d_in[1];   // [4,250,6400]
    if (n_in >= 2 && in_sizes[0] > in_sizes[1]) {
        const float* t = amps; amps = freqs; freqs = t;
    }

    static const size_t scan_smem = (31994 + 256) * sizeof(float);  // ~129 KB
    cudaFuncSetAttribute(scan_kernel,
                         cudaFuncAttributeMaxDynamicSharedMemorySize,
                         (int)scan_smem);

    ctrl_kernel<<<(NROW + CTRL_ROWS - 1) / CTRL_ROWS, CTRL_ROWS>>>(freqs, amps);
    scan_kernel<<<NSEQ, 1024, scan_smem>>>();
    out_kernel<<<dim3((TT + 3) / 4, BB, NSPLIT), 256>>>();
    comb_kernel<<<(BB * SS + 255) / 256, 256>>>((float*)d_out);
}

// round 8
// speedup vs baseline: 7.2622x; 1.0622x over previous
#include <cuda_runtime.h>
#include <math.h>

#define BB   4
#define TT   250
#define NS   100
#define DEP  64
#define SS   64000
#define NROW (BB*TT*NS)      // 100000 frame-rows
#define NSEQ (BB*NS)         // 400 scan sequences
#define L2N  16000           // level-2 scan length per sequence
#define NSPLIT 4
#define NPER (NS/NSPLIT)     // 25 sinusoids per partial
#define CTRL_ROWS 128

__device__ float g_freq[NROW];
__device__ float g_amp[NROW];
__device__ float g_scan2[(size_t)NSEQ * L2N];            // 25.6 MB
__device__ float g_part[(size_t)NSPLIT * BB * SS];       // 4 MB partial sums

// omega(s) for s = k*256 + r, mirroring jax fp32 ops exactly (no FMA contraction)
__device__ __forceinline__ float omega_val(float x0, float x1, int r) {
    float frac = __fmul_rn((float)r, 0.00390625f);
    float fe   = __fadd_rn(__fmul_rn(x0, __fsub_rn(1.0f, frac)),
                           __fmul_rn(x1, frac));
    return __fmul_rn(fe, (float)(6.283185307179586 / 16000.0));
}

// scalar sin for positive phases x < 2.1e5: reduce mod pi (3-part Cody-Waite
// via FMA), odd Taylor poly through x^11 on [-pi/2, pi/2], sign = parity(q).
// |err vs libm sinf| <= ~3e-7 abs. Pure register math.
__device__ __forceinline__ float sin_me(float x) {
    const float INVPI = (float)(1.0 / 3.14159265358979323846);
    const double PID = 3.14159265358979323846;
    const float H1 = (float)PID;
    const float H2 = (float)(PID - (double)H1);
    const float H3 = (float)(PID - (double)H1 - (double)H2);

    float t = __fmul_rn(x, INVPI);
    int   i = __float2int_rn(t);
    float q = (float)i;
    float r = __fmaf_rn(q, -H1, x);
    r = __fmaf_rn(q, -H2, r);
    r = __fmaf_rn(q, -H3, r);
    float s = __fmul_rn(r, r);

    const float S3  = (float)(-1.0 / 6.0);
    const float S5  = (float)( 1.0 / 120.0);
    const float S7  = (float)(-1.0 / 5040.0);
    const float S9  = (float)( 1.0 / 362880.0);
    const float S11 = (float)(-1.0 / 39916800.0);
    float p = S11;
    p = __fmaf_rn(p, s, S9);
    p = __fmaf_rn(p, s, S7);
    p = __fmaf_rn(p, s, S5);
    p = __fmaf_rn(p, s, S3);
    float res = __fmaf_rn(p, __fmul_rn(r, s), r);
    return __int_as_float(__float_as_int(res) ^ (i << 31));
}

// ---------------------------------------------------------------------------
// controls: one THREAD per row (validated R3 numerics — unchanged).
// ---------------------------------------------------------------------------
__global__ void __launch_bounds__(CTRL_ROWS) ctrl_kernel(
        const float* __restrict__ logits,
        const float* __restrict__ amp_in) {
    __shared__ float  sx[CTRL_ROWS * 65];
    __shared__ double dbins[DEP];

    int tid  = threadIdx.x;
    int base = blockIdx.x * CTRL_ROWS;
    int row  = base + tid;

    if (tid < DEP) dbins[tid] = (double)tid / 63.0;

    int nrows = NROW - base; if (nrows > CTRL_ROWS) nrows = CTRL_ROWS;
    int nelem = nrows * DEP;
    const float* src = logits + (size_t)base * DEP;
    for (int i = tid; i < nelem; i += CTRL_ROWS)
        sx[(i >> 6) * 65 + (i & 63)] = src[i];
    __syncthreads();

    if (row >= NROW) return;
    const float* x = sx + tid * 65;

    float m = x[0];
    #pragma unroll
    for (int j = 1; j < DEP; ++j) m = fmaxf(m, x[j]);

    double se = 0.0, seb = 0.0;
    #pragma unroll 8
    for (int j = 0; j < DEP; ++j) {
        float e = expf(__fsub_rn(x[j], m));
        double ed = (double)e;
        se += ed;
        seb = fma(ed, dbins[j], seb);
    }
    float fu = (float)(seb / se);

    const float mminf = (float)15.48682057635244;
    const float mdelf = (float)103.72627427729668;
    float midi = __fadd_rn(mminf, __fmul_rn(fu, mdelf));
    float ex   = __fdiv_rn(__fsub_rn(midi, 69.0f), 12.0f);
    float hz   = __fmul_rn(440.0f, powf(2.0f, ex));
    g_freq[row] = hz;

    float xv = amp_in[row];
    float sg = __fdiv_rn(1.0f, __fadd_rn(1.0f, expf(-xv)));
    float p  = powf(sg, (float)2.302585092994046);
    float a  = __fadd_rn(__fmul_rn(2.0f, p), 1e-7f);
    if (!(hz < 8000.0f)) a = 0.0f;
    g_amp[row] = a;
}

// ---------------------------------------------------------------------------
// associative_scan replica producing the level-2 inclusive scan in smem.
// (exact R3 version — known good)
// ---------------------------------------------------------------------------
__global__ void __launch_bounds__(1024, 1) scan_kernel() {
    extern __shared__ float sm[];            // 31994 level floats + fr[251]
    float* fr = sm + 31994;

    int seq = blockIdx.x;
    int b = seq / NS, n = seq % NS;
    int tid = threadIdx.x;

    for (int t = tid; t < TT; t += 1024)
        fr[t] = g_freq[(b * TT + t) * NS + n];
    __syncthreads();
    if (tid == 0) fr[TT] = fr[TT - 1];       // endpoint clip
    __syncthreads();

    // build level 2 directly: a2[i] = (o0+o1)+(o2+o3); all 4 share frame k
    for (int i = tid; i < L2N; i += 1024) {
        int s = 4 * i;
        int k = s >> 8, r = s & 255;
        float x0 = fr[k], x1 = fr[k + 1];
        float o0 = omega_val(x0, x1, r);
        float o1 = omega_val(x0, x1, r + 1);
        float o2 = omega_val(x0, x1, r + 2);
        float o3 = omega_val(x0, x1, r + 3);
        sm[i] = __fadd_rn(__fadd_rn(o0, o1), __fadd_rn(o2, o3));
    }
    __syncthreads();

    int offs[14], szs[14];
    {
        int o = 0, s = L2N;
        #pragma unroll
        for (int l = 0; l < 14; ++l) { offs[l] = o; szs[l] = s; o += s; s >>= 1; }
    }

    for (int l = 0; l < 13; ++l) {                       // upsweep
        const float* srcp = sm + offs[l];
        float*       dst  = sm + offs[l + 1];
        int m = szs[l + 1];
        for (int i = tid; i < m; i += 1024)
            dst[i] = __fadd_rn(srcp[2 * i], srcp[2 * i + 1]);
        __syncthreads();
    }

    for (int l = 12; l >= 0; --l) {                      // downsweep, in-place
        float*       a  = sm + offs[l];
        const float* sc = sm + offs[l + 1];
        int nl = szs[l];
        for (int j = tid; j < nl; j += 1024) {
            float v;
            if (j & 1)        v = sc[j >> 1];
            else if (j == 0)  v = a[0];
            else              v = __fadd_rn(sc[(j >> 1) - 1], a[j]);
            a[j] = v;
        }
        __syncthreads();
    }

    float* g = g_scan2 + (size_t)seq * L2N;
    for (int i = tid; i < L2N; i += 1024) g[i] = sm[i];
}

// ---------------------------------------------------------------------------
// output: thread = one scan2 cell (4 samples); blockIdx.z = n-split.
// (exact R3 version except sinf -> sin_me)
// ---------------------------------------------------------------------------
__global__ void __launch_bounds__(256) out_kernel() {
    int fg = blockIdx.x;              // frames 4fg .. 4fg+3
    int b  = blockIdx.y;
    int sp = blockIdx.z;
    int t  = threadIdx.x;

    __shared__ float fs[5 * NS], as[5 * NS];
    for (int i = t; i < 5 * NS; i += 256) {
        int fl = i / NS, nn = i % NS;
        int frame = 4 * fg + fl;
        if (frame > TT - 1) frame = TT - 1;
        fs[i] = g_freq[(b * TT + frame) * NS + nn];
        as[i] = g_amp [(b * TT + frame) * NS + nn];
    }
    __syncthreads();

    int kk = t >> 6, j = t & 63;
    int k  = 4 * fg + kk;
    if (k >= TT) return;

    int r0 = 4 * j;
    int q  = k * 64 + j;
    int s0 = k * 256 + r0;

    float w[4], ow[4];
    #pragma unroll
    for (int i = 0; i < 4; ++i) {
        float rf = (float)(r0 + i);
        float warg = __fdiv_rn(__fmul_rn((float)3.141592653589793, rf), 256.0f);
        w[i]  = __fsub_rn(0.5f, __fmul_rn(0.5f, cosf(warg)));
        ow[i] = __fsub_rn(1.0f, w[i]);
    }

    const float* fp0 = fs + kk * NS;
    const float* fp1 = fs + (kk + 1) * NS;
    const float* ap0 = as + kk * NS;
    const float* ap1 = as + (kk + 1) * NS;

    int nb = sp * NPER;
    const float* buf = g_scan2 + ((size_t)(b * NS + nb)) * L2N + q;

    float acc0 = 0.f, acc1 = 0.f, acc2 = 0.f, acc3 = 0.f;
    #pragma unroll 2
    for (int m = 0; m < NPER; ++m) {
        int n = nb + m;
        float f0 = fp0[n], f1 = fp1[n];
        float bq  = buf[(size_t)m * L2N];
        float bm1 = (q > 0) ? buf[(size_t)m * L2N - 1] : 0.0f;

        float o0 = omega_val(f0, f1, r0);
        float o1 = omega_val(f0, f1, r0 + 1);
        float o2 = omega_val(f0, f1, r0 + 2);
        float t01 = __fadd_rn(o0, o1);

        float P0 = q ? __fadd_rn(bm1, o0)  : o0;
        float P1 = q ? __fadd_rn(bm1, t01) : t01;
        float P2 = __fadd_rn(P1, o2);
        float P3 = bq;

        float a0 = ap0[n], a1 = ap1[n];
        float ae0 = __fadd_rn(__fmul_rn(a0, ow[0]), __fmul_rn(a1, w[0]));
        float ae1 = __fadd_rn(__fmul_rn(a0, ow[1]), __fmul_rn(a1, w[1]));
        float ae2 = __fadd_rn(__fmul_rn(a0, ow[2]), __fmul_rn(a1, w[2]));
        float ae3 = __fadd_rn(__fmul_rn(a0, ow[3]), __fmul_rn(a1, w[3]));

        acc0 = __fadd_rn(acc0, __fmul_rn(ae0, sin_me(P0)));
        acc1 = __fadd_rn(acc1, __fmul_rn(ae1, sin_me(P1)));
        acc2 = __fadd_rn(acc2, __fmul_rn(ae2, sin_me(P2)));
        acc3 = __fadd_rn(acc3, __fmul_rn(ae3, sin_me(P3)));
    }

    float4 v; v.x = acc0; v.y = acc1; v.z = acc2; v.w = acc3;
    *(float4*)(g_part + ((size_t)(sp * BB + b)) * SS + s0) = v;
}

// ---------------------------------------------------------------------------
__global__ void comb_kernel(float* __restrict__ out) {
    int i = blockIdx.x * blockDim.x + threadIdx.x;
    if (i < BB * SS) {
        float v = __fadd_rn(__fadd_rn(__fadd_rn(
                      g_part[i],
                      g_part[(size_t)BB * SS + i]),
                      g_part[(size_t)2 * BB * SS + i]),
                      g_part[(size_t)3 * BB * SS + i]);
        out[i] = v;
    }
}

// ---------------------------------------------------------------------------
extern "C" void kernel_launch(void* const* d_in, const int* in_sizes, int n_in,
                              void* d_out, int out_size) {
    const float* amps  = (const float*)d_in[0];   // [4,250,100]
    const float* freqs = (const float*)d_in[1];   // [4,250,6400]
    if (n_in >= 2 && in_sizes[0] > in_sizes[1]) {
        const float* t = amps; amps = freqs; freqs = t;
    }

    static const size_t scan_smem = (31994 + 256) * sizeof(float);  // ~129 KB
    cudaFuncSetAttribute(scan_kernel,
                         cudaFuncAttributeMaxDynamicSharedMemorySize,
                         (int)scan_smem);

    ctrl_kernel<<<(NROW + CTRL_ROWS - 1) / CTRL_ROWS, CTRL_ROWS>>>(freqs, amps);
    scan_kernel<<<NSEQ, 1024, scan_smem>>>();
    out_kernel<<<dim3((TT + 3) / 4, BB, NSPLIT), 256>>>();
    comb_kernel<<<(BB * SS + 255) / 256, 256>>>((float*)d_out);
}

// round 9
// speedup vs baseline: 11.3876x; 1.5681x over previous
#include <cuda_runtime.h>
#include <math.h>

#define BB   4
#define TT   250
#define NS   100
#define DEP  64
#define SS   64000
#define NROW (BB*TT*NS)      // 100000 frame-rows
#define NSEQ (BB*NS)         // 400 scan sequences
#define L3N  8000            // level-3 scan length per sequence
#define NSPLIT 4
#define NPER (NS/NSPLIT)     // 25 sinusoids per partial
#define CTRL_ROWS 128

__device__ float g_freq[NROW];
__device__ float g_amp[NROW];
__device__ float g_scan3[(size_t)NSEQ * L3N];            // 12.8 MB
__device__ float g_part[(size_t)NSPLIT * BB * SS];       // 4 MB partial sums

// omega(s) for s = k*256 + r, mirroring jax fp32 ops exactly (no FMA contraction)
__device__ __forceinline__ float omega_val(float x0, float x1, int r) {
    float frac = __fmul_rn((float)r, 0.00390625f);
    float fe   = __fadd_rn(__fmul_rn(x0, __fsub_rn(1.0f, frac)),
                           __fmul_rn(x1, frac));
    return __fmul_rn(fe, (float)(6.283185307179586 / 16000.0));
}

// scalar sin for positive phases x < 2.1e5: reduce mod pi (3-part Cody-Waite
// via FMA), odd Taylor poly through x^11, sign = parity(q).  <=3e-7 abs err.
__device__ __forceinline__ float sin_me(float x) {
    const float INVPI = (float)(1.0 / 3.14159265358979323846);
    const double PID = 3.14159265358979323846;
    const float H1 = (float)PID;
    const float H2 = (float)(PID - (double)H1);
    const float H3 = (float)(PID - (double)H1 - (double)H2);

    float t = __fmul_rn(x, INVPI);
    int   i = __float2int_rn(t);
    float q = (float)i;
    float r = __fmaf_rn(q, -H1, x);
    r = __fmaf_rn(q, -H2, r);
    r = __fmaf_rn(q, -H3, r);
    float s = __fmul_rn(r, r);

    const float S3  = (float)(-1.0 / 6.0);
    const float S5  = (float)( 1.0 / 120.0);
    const float S7  = (float)(-1.0 / 5040.0);
    const float S9  = (float)( 1.0 / 362880.0);
    const float S11 = (float)(-1.0 / 39916800.0);
    float p = S11;
    p = __fmaf_rn(p, s, S9);
    p = __fmaf_rn(p, s, S7);
    p = __fmaf_rn(p, s, S5);
    p = __fmaf_rn(p, s, S3);
    float res = __fmaf_rn(p, __fmul_rn(r, s), r);
    return __int_as_float(__float_as_int(res) ^ (i << 31));
}

// ---------------------------------------------------------------------------
// controls: one THREAD per row. Softmax sums via double-float (fp32 pair)
// accumulation (TwoSum/TwoProd), ~2e-13 relative — indistinguishable from the
// double result after fp32 rounding except ~0.3/100k rows by 1 ulp.
// ---------------------------------------------------------------------------
__global__ void __launch_bounds__(CTRL_ROWS) ctrl_kernel(
        const float* __restrict__ logits,
        const float* __restrict__ amp_in) {
    __shared__ float  sx[CTRL_ROWS * 65];
    __shared__ float2 bins2[DEP];

    int tid  = threadIdx.x;
    int base = blockIdx.x * CTRL_ROWS;
    int row  = base + tid;

    if (tid < DEP) {
        double bd = (double)tid / 63.0;
        float bh = (float)bd;
        float bl = (float)(bd - (double)bh);
        bins2[tid] = make_float2(bh, bl);
    }

    int nrows = NROW - base; if (nrows > CTRL_ROWS) nrows = CTRL_ROWS;
    int nelem = nrows * DEP;
    const float* src = logits + (size_t)base * DEP;
    for (int i = tid; i < nelem; i += CTRL_ROWS)
        sx[(i >> 6) * 65 + (i & 63)] = src[i];
    __syncthreads();

    if (row >= NROW) return;
    const float* x = sx + tid * 65;

    float m = x[0];
    #pragma unroll
    for (int j = 1; j < DEP; ++j) m = fmaxf(m, x[j]);

    float se_hi = 0.f, se_lo = 0.f, sb_hi = 0.f, sb_lo = 0.f;
    #pragma unroll 8
    for (int j = 0; j < DEP; ++j) {
        float e = expf(__fsub_rn(x[j], m));

        // se += e (df TwoSum + renorm)
        float s  = __fadd_rn(se_hi, e);
        float bv = __fsub_rn(s, se_hi);
        float er = __fadd_rn(__fsub_rn(se_hi, __fsub_rn(s, bv)),
                             __fsub_rn(e, bv));
        float lo = __fadd_rn(se_lo, er);
        se_hi = __fadd_rn(s, lo);
        se_lo = __fsub_rn(lo, __fsub_rn(se_hi, s));

        // p = e * bin (TwoProd with df bin)
        float2 bb = bins2[j];
        float ph = __fmul_rn(e, bb.x);
        float pl = __fmaf_rn(e, bb.x, -ph);
        pl = __fmaf_rn(e, bb.y, pl);

        // sb += (ph, pl)
        s  = __fadd_rn(sb_hi, ph);
        bv = __fsub_rn(s, sb_hi);
        er = __fadd_rn(__fsub_rn(sb_hi, __fsub_rn(s, bv)),
                       __fsub_rn(ph, bv));
        lo = __fadd_rn(__fadd_rn(sb_lo, er), pl);
        sb_hi = __fadd_rn(s, lo);
        sb_lo = __fsub_rn(lo, __fsub_rn(sb_hi, s));
    }
    double se  = (double)se_hi + (double)se_lo;
    double seb = (double)sb_hi + (double)sb_lo;
    float fu = (float)(seb / se);

    const float mminf = (float)15.48682057635244;
    const float mdelf = (float)103.72627427729668;
    float midi = __fadd_rn(mminf, __fmul_rn(fu, mdelf));
    float ex   = __fdiv_rn(__fsub_rn(midi, 69.0f), 12.0f);
    float hz   = __fmul_rn(440.0f, powf(2.0f, ex));
    g_freq[row] = hz;

    float xv = amp_in[row];
    float sg = __fdiv_rn(1.0f, __fadd_rn(1.0f, expf(-xv)));
    float p  = powf(sg, (float)2.302585092994046);
    float a  = __fadd_rn(__fmul_rn(2.0f, p), 1e-7f);
    if (!(hz < 8000.0f)) a = 0.0f;
    g_amp[row] = a;
}

// ---------------------------------------------------------------------------
// associative_scan replica producing the LEVEL-3 inclusive scan in smem
// (65 KB -> 2 blocks/SM). Same strided-loop access patterns as the proven R3
// kernel; only the build level changed (8 omegas per cell, identical add tree).
// ---------------------------------------------------------------------------
__global__ void __launch_bounds__(1024) scan_kernel() {
    extern __shared__ float sm[];            // 15994 level floats + fr[251]
    float* fr = sm + 15994;

    int seq = blockIdx.x;
    int b = seq / NS, n = seq % NS;
    int tid = threadIdx.x;

    for (int t = tid; t < TT; t += 1024)
        fr[t] = g_freq[(b * TT + t) * NS + n];
    __syncthreads();
    if (tid == 0) fr[TT] = fr[TT - 1];       // endpoint clip
    __syncthreads();

    // build level 3 directly: a3[i] = ((o0+o1)+(o2+o3)) + ((o4+o5)+(o6+o7));
    // all 8 samples share frame k (r <= 248).
    for (int i = tid; i < L3N; i += 1024) {
        int s = 8 * i;
        int k = s >> 8, r = s & 255;
        float x0 = fr[k], x1 = fr[k + 1];
        float o0 = omega_val(x0, x1, r);
        float o1 = omega_val(x0, x1, r + 1);
        float o2 = omega_val(x0, x1, r + 2);
        float o3 = omega_val(x0, x1, r + 3);
        float o4 = omega_val(x0, x1, r + 4);
        float o5 = omega_val(x0, x1, r + 5);
        float o6 = omega_val(x0, x1, r + 6);
        float o7 = omega_val(x0, x1, r + 7);
        float a20 = __fadd_rn(__fadd_rn(o0, o1), __fadd_rn(o2, o3));
        float a21 = __fadd_rn(__fadd_rn(o4, o5), __fadd_rn(o6, o7));
        sm[i] = __fadd_rn(a20, a21);
    }
    __syncthreads();

    int offs[13], szs[13];
    {
        int o = 0, s = L3N;
        #pragma unroll
        for (int l = 0; l < 13; ++l) { offs[l] = o; szs[l] = s; o += s; s >>= 1; }
    }

    for (int l = 0; l < 12; ++l) {                       // upsweep
        const float* srcp = sm + offs[l];
        float*       dst  = sm + offs[l + 1];
        int m = szs[l + 1];
        for (int i = tid; i < m; i += 1024)
            dst[i] = __fadd_rn(srcp[2 * i], srcp[2 * i + 1]);
        __syncthreads();
    }

    for (int l = 11; l >= 0; --l) {                      // downsweep, in-place
        float*       a  = sm + offs[l];
        const float* sc = sm + offs[l + 1];
        int nl = szs[l];
        for (int j = tid; j < nl; j += 1024) {
            float v;
            if (j & 1)        v = sc[j >> 1];
            else if (j == 0)  v = a[0];
            else              v = __fadd_rn(sc[(j >> 1) - 1], a[j]);
            a[j] = v;
        }
        __syncthreads();
    }

    float* g = g_scan3 + (size_t)seq * L3N;
    for (int i = tid; i < L3N; i += 1024) g[i] = sm[i];
}

// ---------------------------------------------------------------------------
// output: thread = one scan3 cell (8 samples). Local reconstruction of the
// level-2 downsweep values (bit-identical expressions):
//   P0 = bm + o0          P4 = P3 + o4
//   P1 = bm + (o0+o1)     P5 = P3 + (o4+o5)
//   P2 = P1 + o2          P6 = P5 + o6
//   P3 = bm + a2_0        P7 = scan3[i]
// where bm = scan3[i-1] (0 for i==0) and a2_0 = (o0+o1)+(o2+o3).
// ---------------------------------------------------------------------------
__global__ void __launch_bounds__(256) out_kernel() {
    int bx = blockIdx.x;              // frames 8bx .. 8bx+7
    int b  = blockIdx.y;
    int sp = blockIdx.z;
    int t  = threadIdx.x;

    __shared__ float fs[9 * NS], as[9 * NS];
    for (int i = t; i < 9 * NS; i += 256) {
        int fl = i / NS, nn = i % NS;
        int frame = 8 * bx + fl;
        if (frame > TT - 1) frame = TT - 1;
        fs[i] = g_freq[(b * TT + frame) * NS + nn];
        as[i] = g_amp [(b * TT + frame) * NS + nn];
    }
    __syncthreads();

    int fid = t >> 5, j = t & 31;
    int k   = 8 * bx + fid;
    if (k >= TT) return;

    int r0 = 8 * j;
    int i3 = k * 32 + j;              // scan3 index
    int s0 = k * 256 + r0;

    float w[8], ow[8];
    #pragma unroll
    for (int i = 0; i < 8; ++i) {
        float rf = (float)(r0 + i);
        float warg = __fdiv_rn(__fmul_rn((float)3.141592653589793, rf), 256.0f);
        w[i]  = __fsub_rn(0.5f, __fmul_rn(0.5f, cosf(warg)));
        ow[i] = __fsub_rn(1.0f, w[i]);
    }

    const float* fp0 = fs + fid * NS;
    const float* fp1 = fs + (fid + 1) * NS;
    const float* ap0 = as + fid * NS;
    const float* ap1 = as + (fid + 1) * NS;

    int nb = sp * NPER;
    const float* buf = g_scan3 + ((size_t)(b * NS + nb)) * L3N + i3;

    float acc0 = 0.f, acc1 = 0.f, acc2 = 0.f, acc3 = 0.f;
    float acc4 = 0.f, acc5 = 0.f, acc6 = 0.f, acc7 = 0.f;
    #pragma unroll 2
    for (int m = 0; m < NPER; ++m) {
        int n = nb + m;
        float f0 = fp0[n], f1 = fp1[n];
        float bq = buf[(size_t)m * L3N];
        float bm = (i3 > 0) ? buf[(size_t)m * L3N - 1] : 0.0f;

        float o0 = omega_val(f0, f1, r0);
        float o1 = omega_val(f0, f1, r0 + 1);
        float o2 = omega_val(f0, f1, r0 + 2);
        float o3 = omega_val(f0, f1, r0 + 3);
        float o4 = omega_val(f0, f1, r0 + 4);
        float o5 = omega_val(f0, f1, r0 + 5);
        float o6 = omega_val(f0, f1, r0 + 6);

        float t01 = __fadd_rn(o0, o1);
        float a20 = __fadd_rn(t01, __fadd_rn(o2, o3));
        float t45 = __fadd_rn(o4, o5);

        float P0 = __fadd_rn(bm, o0);     // i3==0: 0+o0 == o0 exactly
        float P1 = __fadd_rn(bm, t01);
        float P2 = __fadd_rn(P1, o2);
        float P3 = __fadd_rn(bm, a20);    // == scan2[2*i3] from old downsweep
        float P4 = __fadd_rn(P3, o4);
        float P5 = __fadd_rn(P3, t45);
        float P6 = __fadd_rn(P5, o6);
        float P7 = bq;                    // == scan2[2*i3+1]

        float a0 = ap0[n], a1 = ap1[n];
        acc0 = __fadd_rn(acc0, __fmul_rn(__fadd_rn(__fmul_rn(a0, ow[0]), __fmul_rn(a1, w[0])), sin_me(P0)));
        acc1 = __fadd_rn(acc1, __fmul_rn(__fadd_rn(__fmul_rn(a0, ow[1]), __fmul_rn(a1, w[1])), sin_me(P1)));
        acc2 = __fadd_rn(acc2, __fmul_rn(__fadd_rn(__fmul_rn(a0, ow[2]), __fmul_rn(a1, w[2])), sin_me(P2)));
        acc3 = __fadd_rn(acc3, __fmul_rn(__fadd_rn(__fmul_rn(a0, ow[3]), __fmul_rn(a1, w[3])), sin_me(P3)));
        acc4 = __fadd_rn(acc4, __fmul_rn(__fadd_rn(__fmul_rn(a0, ow[4]), __fmul_rn(a1, w[4])), sin_me(P4)));
        acc5 = __fadd_rn(acc5, __fmul_rn(__fadd_rn(__fmul_rn(a0, ow[5]), __fmul_rn(a1, w[5])), sin_me(P5)));
        acc6 = __fadd_rn(acc6, __fmul_rn(__fadd_rn(__fmul_rn(a0, ow[6]), __fmul_rn(a1, w[6])), sin_me(P6)));
        acc7 = __fadd_rn(acc7, __fmul_rn(__fadd_rn(__fmul_rn(a0, ow[7]), __fmul_rn(a1, w[7])), sin_me(P7)));
    }

    float* op = g_part + ((size_t)(sp * BB + b)) * SS + s0;
    float4 v0; v0.x = acc0; v0.y = acc1; v0.z = acc2; v0.w = acc3;
    float4 v1; v1.x = acc4; v1.y = acc5; v1.z = acc6; v1.w = acc7;
    *(float4*)(op)     = v0;
    *(float4*)(op + 4) = v1;
}

// ---------------------------------------------------------------------------
__global__ void comb_kernel(float* __restrict__ out) {
    int i = blockIdx.x * blockDim.x + threadIdx.x;
    if (i < BB * SS) {
        float v = __fadd_rn(__fadd_rn(__fadd_rn(
                      g_part[i],
                      g_part[(size_t)BB * SS + i]),
                      g_part[(size_t)2 * BB * SS + i]),
                      g_part[(size_t)3 * BB * SS + i]);
        out[i] = v;
    }
}

// ---------------------------------------------------------------------------
extern "C" void kernel_launch(void* const* d_in, const int* in_sizes, int n_in,
                              void* d_out, int out_size) {
    const float* amps  = (const float*)d_in[0];   // [4,250,100]
    const float* freqs = (const float*)d_in[1];   // [4,250,6400]
    if (n_in >= 2 && in_sizes[0] > in_sizes[1]) {
        const float* t = amps; amps = freqs; freqs = t;
    }

    static const size_t scan_smem = (15994 + 256) * sizeof(float);  // ~65 KB
    cudaFuncSetAttribute(scan_kernel,
                         cudaFuncAttributeMaxDynamicSharedMemorySize,
                         (int)scan_smem);

    ctrl_kernel<<<(NROW + CTRL_ROWS - 1) / CTRL_ROWS, CTRL_ROWS>>>(freqs, amps);
    scan_kernel<<<NSEQ, 1024, scan_smem>>>();
    out_kernel<<<dim3((TT + 7) / 8, BB, NSPLIT), 256>>>();
    comb_kernel<<<(BB * SS + 255) / 256, 256>>>((float*)d_out);
}

// round 10
// speedup vs baseline: 12.0220x; 1.0557x over previous
#include <cuda_runtime.h>
#include <math.h>

#define BB   4
#define TT   250
#define NS   100
#define DEP  64
#define SS   64000
#define NROW (BB*TT*NS)      // 100000 frame-rows
#define NSEQ (BB*NS)         // 400 scan sequences
#define L3N  8000            // level-3 scan length per sequence
#define NSPLIT 4
#define NPER (NS/NSPLIT)     // 25 sinusoids per partial
#define CTRL_ROWS 128

typedef unsigned long long u64;

__device__ float g_freq[NROW];
__device__ float g_amp[NROW];
__device__ float g_scan3[(size_t)NSEQ * L3N];            // 12.8 MB
__device__ float g_part[(size_t)NSPLIT * BB * SS];       // 4 MB partial sums

// omega(s) for s = k*256 + r, mirroring jax fp32 ops exactly (no FMA contraction)
__device__ __forceinline__ float omega_val(float x0, float x1, int r) {
    float frac = __fmul_rn((float)r, 0.00390625f);
    float fe   = __fadd_rn(__fmul_rn(x0, __fsub_rn(1.0f, frac)),
                           __fmul_rn(x1, frac));
    return __fmul_rn(fe, (float)(6.283185307179586 / 16000.0));
}

// ---------------- packed f32x2 helpers (per-lane IEEE rn, bit-exact) -------
__device__ __forceinline__ u64 pk2(float lo, float hi) {
    u64 r; asm("mov.b64 %0,{%1,%2};" : "=l"(r) : "f"(lo), "f"(hi)); return r;
}
__device__ __forceinline__ void up2(u64 v, float& lo, float& hi) {
    asm("mov.b64 {%0,%1},%2;" : "=f"(lo), "=f"(hi) : "l"(v));
}
__device__ __forceinline__ u64 fma2_(u64 a, u64 b, u64 c) {
    u64 d; asm("fma.rn.f32x2 %0,%1,%2,%3;" : "=l"(d) : "l"(a), "l"(b), "l"(c)); return d;
}
__device__ __forceinline__ u64 mul2_(u64 a, u64 b) {
    u64 d; asm("mul.rn.f32x2 %0,%1,%2;" : "=l"(d) : "l"(a), "l"(b)); return d;
}
__device__ __forceinline__ u64 add2_(u64 a, u64 b) {
    u64 d; asm("add.rn.f32x2 %0,%1,%2;" : "=l"(d) : "l"(a), "l"(b)); return d;
}

// packed sin: per-lane identical ops to the validated scalar sin_me
// (3-step Cody-Waite mod pi, Taylor to x^11, sign = parity(q)).
__device__ __forceinline__ u64 sin2me(u64 x) {
    const float INVPI = (float)(1.0 / 3.14159265358979323846);
    const double PID = 3.14159265358979323846;
    const float H1 = (float)PID;
    const float H2 = (float)(PID - (double)H1);
    const float H3 = (float)(PID - (double)H1 - (double)H2);

    u64 t = mul2_(x, pk2(INVPI, INVPI));
    float tl, th; up2(t, tl, th);
    int il = __float2int_rn(tl), ih = __float2int_rn(th);
    u64 q = pk2((float)il, (float)ih);
    u64 r = fma2_(q, pk2(-H1, -H1), x);
    r = fma2_(q, pk2(-H2, -H2), r);
    r = fma2_(q, pk2(-H3, -H3), r);
    u64 s = mul2_(r, r);

    const float S3  = (float)(-1.0 / 6.0);
    const float S5  = (float)( 1.0 / 120.0);
    const float S7  = (float)(-1.0 / 5040.0);
    const float S9  = (float)( 1.0 / 362880.0);
    const float S11 = (float)(-1.0 / 39916800.0);
    u64 p = pk2(S11, S11);
    p = fma2_(p, s, pk2(S9, S9));
    p = fma2_(p, s, pk2(S7, S7));
    p = fma2_(p, s, pk2(S5, S5));
    p = fma2_(p, s, pk2(S3, S3));
    u64 res = fma2_(p, mul2_(r, s), r);

    unsigned sl = ((unsigned)il) << 31;
    unsigned sh = ((unsigned)ih) << 31;
    u64 m; asm("mov.b64 %0,{%1,%2};" : "=l"(m) : "r"(sl), "r"(sh));
    return res ^ m;
}

// ---------------------------------------------------------------------------
// controls: unchanged from passing R9 (df softmax accumulation).
// ---------------------------------------------------------------------------
__global__ void __launch_bounds__(CTRL_ROWS) ctrl_kernel(
        const float* __restrict__ logits,
        const float* __restrict__ amp_in) {
    __shared__ float  sx[CTRL_ROWS * 65];
    __shared__ float2 bins2[DEP];

    int tid  = threadIdx.x;
    int base = blockIdx.x * CTRL_ROWS;
    int row  = base + tid;

    if (tid < DEP) {
        double bd = (double)tid / 63.0;
        float bh = (float)bd;
        float bl = (float)(bd - (double)bh);
        bins2[tid] = make_float2(bh, bl);
    }

    int nrows = NROW - base; if (nrows > CTRL_ROWS) nrows = CTRL_ROWS;
    int nelem = nrows * DEP;
    const float* src = logits + (size_t)base * DEP;
    for (int i = tid; i < nelem; i += CTRL_ROWS)
        sx[(i >> 6) * 65 + (i & 63)] = src[i];
    __syncthreads();

    if (row >= NROW) return;
    const float* x = sx + tid * 65;

    float m = x[0];
    #pragma unroll
    for (int j = 1; j < DEP; ++j) m = fmaxf(m, x[j]);

    float se_hi = 0.f, se_lo = 0.f, sb_hi = 0.f, sb_lo = 0.f;
    #pragma unroll 8
    for (int j = 0; j < DEP; ++j) {
        float e = expf(__fsub_rn(x[j], m));

        float s  = __fadd_rn(se_hi, e);
        float bv = __fsub_rn(s, se_hi);
        float er = __fadd_rn(__fsub_rn(se_hi, __fsub_rn(s, bv)),
                             __fsub_rn(e, bv));
        float lo = __fadd_rn(se_lo, er);
        se_hi = __fadd_rn(s, lo);
        se_lo = __fsub_rn(lo, __fsub_rn(se_hi, s));

        float2 bb = bins2[j];
        float ph = __fmul_rn(e, bb.x);
        float pl = __fmaf_rn(e, bb.x, -ph);
        pl = __fmaf_rn(e, bb.y, pl);

        s  = __fadd_rn(sb_hi, ph);
        bv = __fsub_rn(s, sb_hi);
        er = __fadd_rn(__fsub_rn(sb_hi, __fsub_rn(s, bv)),
                       __fsub_rn(ph, bv));
        lo = __fadd_rn(__fadd_rn(sb_lo, er), pl);
        sb_hi = __fadd_rn(s, lo);
        sb_lo = __fsub_rn(lo, __fsub_rn(sb_hi, s));
    }
    double se  = (double)se_hi + (double)se_lo;
    double seb = (double)sb_hi + (double)sb_lo;
    float fu = (float)(seb / se);

    const float mminf = (float)15.48682057635244;
    const float mdelf = (float)103.72627427729668;
    float midi = __fadd_rn(mminf, __fmul_rn(fu, mdelf));
    float ex   = __fdiv_rn(__fsub_rn(midi, 69.0f), 12.0f);
    float hz   = __fmul_rn(440.0f, powf(2.0f, ex));
    g_freq[row] = hz;

    float xv = amp_in[row];
    float sg = __fdiv_rn(1.0f, __fadd_rn(1.0f, expf(-xv)));
    float p  = powf(sg, (float)2.302585092994046);
    float a  = __fadd_rn(__fmul_rn(2.0f, p), 1e-7f);
    if (!(hz < 8000.0f)) a = 0.0f;
    g_amp[row] = a;
}

// ---------------------------------------------------------------------------
// scan: unchanged from passing R9 (level-3 inclusive scan, 65 KB smem).
// ---------------------------------------------------------------------------
__global__ void __launch_bounds__(1024) scan_kernel() {
    extern __shared__ float sm[];            // 15994 level floats + fr[251]
    float* fr = sm + 15994;

    int seq = blockIdx.x;
    int b = seq / NS, n = seq % NS;
    int tid = threadIdx.x;

    for (int t = tid; t < TT; t += 1024)
        fr[t] = g_freq[(b * TT + t) * NS + n];
    __syncthreads();
    if (tid == 0) fr[TT] = fr[TT - 1];
    __syncthreads();

    for (int i = tid; i < L3N; i += 1024) {
        int s = 8 * i;
        int k = s >> 8, r = s & 255;
        float x0 = fr[k], x1 = fr[k + 1];
        float o0 = omega_val(x0, x1, r);
        float o1 = omega_val(x0, x1, r + 1);
        float o2 = omega_val(x0, x1, r + 2);
        float o3 = omega_val(x0, x1, r + 3);
        float o4 = omega_val(x0, x1, r + 4);
        float o5 = omega_val(x0, x1, r + 5);
        float o6 = omega_val(x0, x1, r + 6);
        float o7 = omega_val(x0, x1, r + 7);
        float a20 = __fadd_rn(__fadd_rn(o0, o1), __fadd_rn(o2, o3));
        float a21 = __fadd_rn(__fadd_rn(o4, o5), __fadd_rn(o6, o7));
        sm[i] = __fadd_rn(a20, a21);
    }
    __syncthreads();

    int offs[13], szs[13];
    {
        int o = 0, s = L3N;
        #pragma unroll
        for (int l = 0; l < 13; ++l) { offs[l] = o; szs[l] = s; o += s; s >>= 1; }
    }

    for (int l = 0; l < 12; ++l) {
        const float* srcp = sm + offs[l];
        float*       dst  = sm + offs[l + 1];
        int m = szs[l + 1];
        for (int i = tid; i < m; i += 1024)
            dst[i] = __fadd_rn(srcp[2 * i], srcp[2 * i + 1]);
        __syncthreads();
    }

    for (int l = 11; l >= 0; --l) {
        float*       a  = sm + offs[l];
        const float* sc = sm + offs[l + 1];
        int nl = szs[l];
        for (int j = tid; j < nl; j += 1024) {
            float v;
            if (j & 1)        v = sc[j >> 1];
            else if (j == 0)  v = a[0];
            else              v = __fadd_rn(sc[(j >> 1) - 1], a[j]);
            a[j] = v;
        }
        __syncthreads();
    }

    float* g = g_scan3 + (size_t)seq * L3N;
    for (int i = tid; i < L3N; i += 1024) g[i] = sm[i];
}

// ---------------------------------------------------------------------------
// output: thread = one scan3 cell (8 samples), packed f32x2 math on the
// dual-rate fp32 pipe. Phase chain scalar & bit-identical to R9; omega and
// sin per-lane identical; only acc uses fma2 (amplitude-path, ~1e-8).
// ---------------------------------------------------------------------------
__global__ void __launch_bounds__(256) out_kernel() {
    int bx = blockIdx.x;              // frames 8bx .. 8bx+7
    int b  = blockIdx.y;
    int sp = blockIdx.z;
    int t  = threadIdx.x;

    __shared__ float fs[9 * NS], as[9 * NS];
    for (int i = t; i < 9 * NS; i += 256) {
        int fl = i / NS, nn = i % NS;
        int frame = 8 * bx + fl;
        if (frame > TT - 1) frame = TT - 1;
        fs[i] = g_freq[(b * TT + frame) * NS + nn];
        as[i] = g_amp [(b * TT + frame) * NS + nn];
    }
    __syncthreads();

    int fid = t >> 5, j = t & 31;
    int k   = 8 * bx + fid;
    if (k >= TT) return;

    int r0 = 8 * j;
    int i3 = k * 32 + j;              // scan3 index
    int s0 = k * 256 + r0;

    // per-thread packed constants
    float fr_[8], om_[8], w_[8], ow_[8];
    #pragma unroll
    for (int i = 0; i < 8; ++i) {
        float rf = (float)(r0 + i);
        fr_[i] = __fmul_rn(rf, 0.00390625f);
        om_[i] = __fsub_rn(1.0f, fr_[i]);
        float warg = __fdiv_rn(__fmul_rn((float)3.141592653589793, rf), 256.0f);
        w_[i]  = __fsub_rn(0.5f, __fmul_rn(0.5f, cosf(warg)));
        ow_[i] = __fsub_rn(1.0f, w_[i]);
    }
    u64 frv[4], omv[4], wv[4], owv[4];
    #pragma unroll
    for (int i = 0; i < 4; ++i) {
        frv[i] = pk2(fr_[2*i], fr_[2*i+1]);
        omv[i] = pk2(om_[2*i], om_[2*i+1]);
        wv[i]  = pk2(w_[2*i],  w_[2*i+1]);
        owv[i] = pk2(ow_[2*i], ow_[2*i+1]);
    }
    const float C2PI = (float)(6.283185307179586 / 16000.0);
    u64 c2piv = pk2(C2PI, C2PI);

    const float* fp0 = fs + fid * NS;
    const float* fp1 = fs + (fid + 1) * NS;
    const float* ap0 = as + fid * NS;
    const float* ap1 = as + (fid + 1) * NS;

    int nb = sp * NPER;
    const float* buf = g_scan3 + ((size_t)(b * NS + nb)) * L3N + i3;

    u64 acc[4];
    acc[0] = acc[1] = acc[2] = acc[3] = pk2(0.f, 0.f);

    #pragma unroll 2
    for (int m = 0; m < NPER; ++m) {
        int n = nb + m;
        float f0 = fp0[n], f1 = fp1[n];
        u64 x0v = pk2(f0, f0), x1v = pk2(f1, f1);

        // omegas as pairs — per lane: mul, mul, add, mul (bit-exact)
        u64 o01 = mul2_(add2_(mul2_(x0v, omv[0]), mul2_(x1v, frv[0])), c2piv);
        u64 o23 = mul2_(add2_(mul2_(x0v, omv[1]), mul2_(x1v, frv[1])), c2piv);
        u64 o45 = mul2_(add2_(mul2_(x0v, omv[2]), mul2_(x1v, frv[2])), c2piv);
        u64 o67 = mul2_(add2_(mul2_(x0v, omv[3]), mul2_(x1v, frv[3])), c2piv);

        float o0, o1, o2, o3, o4, o5, o6, o7u;
        up2(o01, o0, o1); up2(o23, o2, o3);
        up2(o45, o4, o5); up2(o67, o6, o7u);

        float t01 = __fadd_rn(o0, o1);
        float a20 = __fadd_rn(t01, __fadd_rn(o2, o3));
        float t45 = __fadd_rn(o4, o5);

        float bq = buf[(size_t)m * L3N];
        float bm = (i3 > 0) ? buf[(size_t)m * L3N - 1] : 0.0f;

        float P0 = __fadd_rn(bm, o0);
        float P1 = __fadd_rn(bm, t01);
        float P2 = __fadd_rn(P1, o2);
        float P3 = __fadd_rn(bm, a20);
        float P4 = __fadd_rn(P3, o4);
        float P5 = __fadd_rn(P3, t45);
        float P6 = __fadd_rn(P5, o6);
        float P7 = bq;

        u64 s01 = sin2me(pk2(P0, P1));
        u64 s23 = sin2me(pk2(P2, P3));
        u64 s45 = sin2me(pk2(P4, P5));
        u64 s67 = sin2me(pk2(P6, P7));

        float a0 = ap0[n], a1 = ap1[n];
        u64 a0v = pk2(a0, a0), a1v = pk2(a1, a1);
        // amp env: exact mul/mul/add per lane (matches reference rounding)
        u64 ae01 = add2_(mul2_(a0v, owv[0]), mul2_(a1v, wv[0]));
        u64 ae23 = add2_(mul2_(a0v, owv[1]), mul2_(a1v, wv[1]));
        u64 ae45 = add2_(mul2_(a0v, owv[2]), mul2_(a1v, wv[2]));
        u64 ae67 = add2_(mul2_(a0v, owv[3]), mul2_(a1v, wv[3]));

        acc[0] = fma2_(ae01, s01, acc[0]);
        acc[1] = fma2_(ae23, s23, acc[1]);
        acc[2] = fma2_(ae45, s45, acc[2]);
        acc[3] = fma2_(ae67, s67, acc[3]);
    }

    float* op = g_part + ((size_t)(sp * BB + b)) * SS + s0;
    float lo, hi;
    up2(acc[0], lo, hi); op[0] = lo; op[1] = hi;
    up2(acc[1], lo, hi); op[2] = lo; op[3] = hi;
    up2(acc[2], lo, hi); op[4] = lo; op[5] = hi;
    up2(acc[3], lo, hi); op[6] = lo; op[7] = hi;
}

// ---------------------------------------------------------------------------
__global__ void comb_kernel(float* __restrict__ out) {
    int i = blockIdx.x * blockDim.x + threadIdx.x;
    if (i < BB * SS) {
        float v = __fadd_rn(__fadd_rn(__fadd_rn(
                      g_part[i],
                      g_part[(size_t)BB * SS + i]),
                      g_part[(size_t)2 * BB * SS + i]),
                      g_part[(size_t)3 * BB * SS + i]);
        out[i] = v;
    }
}

// ---------------------------------------------------------------------------
extern "C" void kernel_launch(void* const* d_in, const int* in_sizes, int n_in,
                              void* d_out, int out_size) {
    const float* amps  = (const float*)d_in[0];   // [4,250,100]
    const float* freqs = (const float*)d_in[1];   // [4,250,6400]
    if (n_in >= 2 && in_sizes[0] > in_sizes[1]) {
        const float* t = amps; amps = freqs; freqs = t;
    }

    static const size_t scan_smem = (15994 + 256) * sizeof(float);  // ~65 KB
    cudaFuncSetAttribute(scan_kernel,
                         cudaFuncAttributeMaxDynamicSharedMemorySize,
                         (int)scan_smem);

    ctrl_kernel<<<(NROW + CTRL_ROWS - 1) / CTRL_ROWS, CTRL_ROWS>>>(freqs, amps);
    scan_kernel<<<NSEQ, 1024, scan_smem>>>();
    out_kernel<<<dim3((TT + 7) / 8, BB, NSPLIT), 256>>>();
    comb_kernel<<<(BB * SS + 255) / 256, 256>>>((float*)d_out);
}